// round 12
// baseline (speedup 1.0000x reference)
#include <cuda_runtime.h>
#include <cuda_fp16.h>
#include <cstdint>
#include <cstddef>

#define K_DIM 4096
#define N_DIM 11008
#define M_DIM 4096
#define QROWS (K_DIM / 8)

#define BM 128
#define BN 128
#define BK 64
#define A_ST (BK + 8)                 // 72 halves = 144B stride, conflict-free
#define A_TILE_H (BM * A_ST)          // 9216 halves = 18432 B
#define B_TILE_BYTES 4096             // 8 qweight rows x 128 cols x int32
#define NSTAGE 4
#define STAGE_BYTES (A_TILE_H * 2 + B_TILE_BYTES)   // 22528
#define SMEM_BYTES (NSTAGE * STAGE_BYTES)           // 90112

// x as fp16 (device-code refs only — host symbol address is the ATS host shadow!)
__device__ __half g_X[(size_t)M_DIM * K_DIM];

// ---------------------------------------------------------------------------
// Prep: x fp32 -> fp16 (weights are now dequantized inside the GEMM).
// ---------------------------------------------------------------------------
__global__ void prep_kernel(const float* __restrict__ x) {
    size_t i = ((size_t)blockIdx.x * blockDim.x + threadIdx.x) * 4;
    float4 v = *reinterpret_cast<const float4*>(x + i);
    *reinterpret_cast<__half2*>(&g_X[i]) = __floats2half2_rn(v.x, v.y);
    *reinterpret_cast<__half2*>(&g_X[i + 2]) = __floats2half2_rn(v.z, v.w);
}

// ---------------------------------------------------------------------------
// Fused int4-dequant GEMM: C = x * dequant(qweight) + bias
// 128x128x64 tile, 8 warps (2x4, warp tile 64x32), 4-stage cp.async.
// ---------------------------------------------------------------------------
__device__ __forceinline__ void cp16(uint32_t s, const void* g) {
    asm volatile("cp.async.cg.shared.global [%0], [%1], 16;\n" ::"r"(s), "l"(g) : "memory");
}

__device__ __forceinline__ void issue_tile(int tid, uint32_t sa, uint32_t sb,
                                           const __half* Ag, const int* qwg, int kt) {
    int k0 = kt * BK;
#pragma unroll
    for (int t = 0; t < 4; t++) {               // A: 128 rows x 8 chunks
        int ci = tid + t * 256;
        int ar = ci >> 3, ac = (ci & 7) << 3;
        cp16(sa + (ar * A_ST + ac) * 2, Ag + (size_t)ar * K_DIM + k0 + ac);
    }
    {                                           // B: 8 qweight rows x 128 int32
        int j = tid >> 5;                       // 0..7
        int n4 = (tid & 31) << 2;               // 0,4,...,124
        cp16(sb + (j * 128 + n4) * 4, qwg + (size_t)(kt * 8 + j) * N_DIM + n4);
    }
    asm volatile("cp.async.commit_group;\n" ::: "memory");
}

__device__ __forceinline__ void load_afrags(uint32_t sa, int wm, int lane, int ks,
                                            uint32_t af[4][4]) {
#pragma unroll
    for (int mi = 0; mi < 4; mi++) {
        int m = wm * 64 + mi * 16 + (lane & 15);
        int kc = ks * 16 + ((lane >> 4) << 3);
        uint32_t addr = sa + (m * A_ST + kc) * 2;
        asm volatile("ldmatrix.sync.aligned.m8n8.x4.shared.b16 {%0,%1,%2,%3}, [%4];\n"
                     : "=r"(af[mi][0]), "=r"(af[mi][1]), "=r"(af[mi][2]), "=r"(af[mi][3])
                     : "r"(addr));
    }
}

// Build B fragments in registers from packed int4 (exact reference dequant:
// (1024+q) - (1024+z) exact in fp16, then one fp16 multiply by s).
__device__ __forceinline__ void load_bfrags(uint32_t sb, int wn, int lane, int ks,
                                            const __half2 hz[4], const __half2 hs[4],
                                            uint32_t bf[2][4]) {
    int i8 = (lane & 3) * 8;
    uint32_t base = sb + ((2 * ks) * 128 + wn * 32 + (lane >> 2)) * 4;
#pragma unroll
    for (int ni = 0; ni < 4; ni++) {
        uint32_t addr = base + ni * 32;         // +8 words per ni
        uint32_t w0, w1;
        asm volatile("ld.shared.u32 %0, [%1];" : "=r"(w0) : "r"(addr));
        asm volatile("ld.shared.u32 %0, [%1];" : "=r"(w1) : "r"(addr + 512));
        uint32_t t0 = w0 >> i8;
        uint32_t p0 = (t0 & 0xFu) | ((t0 << 12) & 0x000F0000u) | 0x64006400u;
        uint32_t t1 = w1 >> i8;
        uint32_t p1 = (t1 & 0xFu) | ((t1 << 12) & 0x000F0000u) | 0x64006400u;
        __half2 v0 = __hmul2(__hsub2(*reinterpret_cast<__half2*>(&p0), hz[ni]), hs[ni]);
        __half2 v1 = __hmul2(__hsub2(*reinterpret_cast<__half2*>(&p1), hz[ni]), hs[ni]);
        bf[ni >> 1][(ni & 1) * 2] = *reinterpret_cast<uint32_t*>(&v0);
        bf[ni >> 1][(ni & 1) * 2 + 1] = *reinterpret_cast<uint32_t*>(&v1);
    }
}

__device__ __forceinline__ void do_mmas(const uint32_t af[4][4], const uint32_t bf[2][4],
                                        float acc[4][4][4]) {
#pragma unroll
    for (int mi = 0; mi < 4; mi++)
#pragma unroll
        for (int ni = 0; ni < 4; ni++) {
            uint32_t b0 = bf[ni >> 1][(ni & 1) * 2];
            uint32_t b1 = bf[ni >> 1][(ni & 1) * 2 + 1];
            asm volatile(
                "mma.sync.aligned.m16n8k16.row.col.f32.f16.f16.f32 "
                "{%0,%1,%2,%3}, {%4,%5,%6,%7}, {%8,%9}, {%0,%1,%2,%3};\n"
                : "+f"(acc[mi][ni][0]), "+f"(acc[mi][ni][1]), "+f"(acc[mi][ni][2]),
                  "+f"(acc[mi][ni][3])
                : "r"(af[mi][0]), "r"(af[mi][1]), "r"(af[mi][2]), "r"(af[mi][3]),
                  "r"(b0), "r"(b1));
        }
}

__global__ void __launch_bounds__(256, 2)
gemm_kernel(const int* __restrict__ qw, const int* __restrict__ qz,
            const float* __restrict__ sc, const float* __restrict__ bias,
            float* __restrict__ C) {
    extern __shared__ __align__(16) char smem[];

    const int tid = threadIdx.x;
    const int lane = tid & 31;
    const int warp = tid >> 5;
    const int wm = warp >> 2;   // 0..1
    const int wn = warp & 3;    // 0..3
    const int bn = blockIdx.x;
    const int bm = blockIdx.y;

    const __half* Ag = g_X + (size_t)bm * BM * K_DIM;
    const int* qwg = qw + bn * BN;              // column block base

    uint32_t sA[NSTAGE], sB[NSTAGE];
#pragma unroll
    for (int s = 0; s < NSTAGE; s++) {
        sA[s] = (uint32_t)__cvta_generic_to_shared(smem + s * STAGE_BYTES);
        sB[s] = sA[s] + A_TILE_H * 2;
    }

    float acc[4][4][4];
#pragma unroll
    for (int i = 0; i < 4; i++)
#pragma unroll
        for (int j = 0; j < 4; j++)
#pragma unroll
            for (int k = 0; k < 4; k++) acc[i][j][k] = 0.0f;

    const int NKI = K_DIM / BK;  // 64
    issue_tile(tid, sA[0], sB[0], Ag, qwg, 0);
    issue_tile(tid, sA[1], sB[1], Ag, qwg, 1);
    issue_tile(tid, sA[2], sB[2], Ag, qwg, 2);

    uint32_t af[2][4][4], bf[2][4];
    __half2 hz[4], hs[4];

    for (int kt = 0; kt < NKI; kt++) {
        // Per-group zero/scale regs (group = kt/2, constant across the tile).
        if ((kt & 1) == 0) {
            int g = kt >> 1;
#pragma unroll
            for (int ni = 0; ni < 4; ni++) {
                int n = bn * BN + wn * 32 + ni * 8 + (lane >> 2);
                int z = (qz[g * (N_DIM / 8) + (n >> 3)] >> ((n & 7) * 4)) & 15;
                hz[ni] = __half2half2(__int2half_rn(1024 + z));
                hs[ni] = __half2half2(__float2half_rn(sc[g * N_DIM + n]));
            }
        }

        asm volatile("cp.async.wait_group 2;\n" ::: "memory");
        __syncthreads();
        int cur = kt % NSTAGE;

        load_afrags(sA[cur], wm, lane, 0, af[0]);

        if (kt + 3 < NKI)
            issue_tile(tid, sA[(kt + 3) % NSTAGE], sB[(kt + 3) % NSTAGE], Ag, qwg, kt + 3);

#pragma unroll
        for (int ks = 0; ks < 4; ks++) {
            if (ks < 3) load_afrags(sA[cur], wm, lane, ks + 1, af[(ks + 1) & 1]);
            load_bfrags(sB[cur], wn, lane, ks, hz, hs, bf);
            do_mmas(af[ks & 1], bf, acc);
        }
    }

    // Epilogue: fp16(acc) + fp16(bias) in fp16 (reference semantics), widen to fp32.
#pragma unroll
    for (int mi = 0; mi < 4; mi++) {
        int r = bm * BM + wm * 64 + mi * 16 + (lane >> 2);
#pragma unroll
        for (int ni = 0; ni < 4; ni++) {
            int col = bn * BN + wn * 32 + ni * 8 + (lane & 3) * 2;
            __half b0 = __float2half_rn(bias[col]);
            __half b1 = __float2half_rn(bias[col + 1]);
            float2 v0, v1;
            v0.x = __half2float(__hadd(__float2half_rn(acc[mi][ni][0]), b0));
            v0.y = __half2float(__hadd(__float2half_rn(acc[mi][ni][1]), b1));
            v1.x = __half2float(__hadd(__float2half_rn(acc[mi][ni][2]), b0));
            v1.y = __half2float(__hadd(__float2half_rn(acc[mi][ni][3]), b1));
            *reinterpret_cast<float2*>(C + (size_t)r * N_DIM + col) = v0;
            *reinterpret_cast<float2*>(C + (size_t)(r + 8) * N_DIM + col) = v1;
        }
    }
}

extern "C" void kernel_launch(void* const* d_in, const int* in_sizes, int n_in,
                              void* d_out, int out_size) {
    const float* x = nullptr;
    const int* qw = nullptr;
    const int* qz = nullptr;
    const float* sc = nullptr;
    const float* bias = nullptr;
    for (int i = 0; i < n_in; i++) {
        int sz = in_sizes[i];
        if (sz == QROWS * N_DIM) qw = (const int*)d_in[i];
        else if (sz == 32 * (N_DIM / 8)) qz = (const int*)d_in[i];
        else if (sz == 32 * N_DIM) sc = (const float*)d_in[i];
        else if (sz == N_DIM) bias = (const float*)d_in[i];
        else if (sz == M_DIM * K_DIM) x = (const float*)d_in[i];
    }
    float* out = (float*)d_out;

    prep_kernel<<<M_DIM * K_DIM / 1024, 256>>>(x);

    cudaFuncSetAttribute(gemm_kernel, cudaFuncAttributeMaxDynamicSharedMemorySize,
                         SMEM_BYTES);
    dim3 g_grid(N_DIM / BN, M_DIM / BM);  // (86, 32)
    gemm_kernel<<<g_grid, 256, SMEM_BYTES>>>(qw, qz, sc, bias, out);
}

// round 13
// speedup vs baseline: 1.0281x; 1.0281x over previous
#include <cuda_runtime.h>
#include <cuda_fp16.h>
#include <cstdint>
#include <cstddef>

#define K_DIM 4096
#define N_DIM 11008
#define M_DIM 4096
#define QROWS (K_DIM / 8)

#define BM 128
#define BN 128
#define BK 64
#define A_ST (BK + 8)                 // 72 halves = 144B stride, conflict-free
#define A_TILE_H (BM * A_ST)          // 9216 halves = 18432 B
#define B_TILE_BYTES 4096             // 128 n-rows x 8 repacked words x 4B
#define NSTAGE 4
#define STAGE_BYTES (A_TILE_H * 2 + B_TILE_BYTES)   // 22528
#define SMEM_BYTES (NSTAGE * STAGE_BYTES)           // 90112

// Device-code-only globals (host symbol address = ATS host shadow = zeros!).
__device__ __half g_X[(size_t)M_DIM * K_DIM];        // x as fp16 [M, K]
__device__ uint32_t g_RQ[(size_t)N_DIM * QROWS];     // repacked qweight [N][QROWS]

// ---------------------------------------------------------------------------
// Prep: blocks [0,NCVT) convert x fp32->fp16; blocks [NCVT,+NRP) repack
// qweight into [n][kk] n-major with nibble interleave:
//   rw low16  = q0|q2<<4|q4<<8|q6<<12,  rw high16 = q1|q3<<4|q5<<8|q7<<12
// so (rw>>4c) & 0x000F000F == (q_{2c}, q_{2c+1}) — one SHF+LOP3 per half2.
// ---------------------------------------------------------------------------
#define NCVT (M_DIM * K_DIM / 1024)   // 16384
#define NRP (16 * 43)                 // kk-tiles(512/32) x n-tiles(11008/256)

__device__ __forceinline__ uint32_t interleave_nibbles(uint32_t w) {
    uint32_t e = w & 0x0F0F0F0Fu;
    e = e | (e >> 4); e &= 0x00FF00FFu; e = e | (e >> 8);
    uint32_t o = (w >> 4) & 0x0F0F0F0Fu;
    o = o | (o >> 4); o &= 0x00FF00FFu; o = o | (o >> 8);
    return (e & 0xFFFFu) | (o << 16);
}

__global__ void prep_kernel(const float* __restrict__ x, const int* __restrict__ qw) {
    __shared__ uint32_t ts[32][257];
    int b = blockIdx.x;
    int tid = threadIdx.x;
    if (b < NCVT) {
        size_t i = ((size_t)b * 256 + tid) * 4;
        float4 v = *reinterpret_cast<const float4*>(x + i);
        *reinterpret_cast<__half2*>(&g_X[i]) = __floats2half2_rn(v.x, v.y);
        *reinterpret_cast<__half2*>(&g_X[i + 2]) = __floats2half2_rn(v.z, v.w);
        return;
    }
    int b2 = b - NCVT;
    int kkb = b2 & 15;              // 32-row kk tile
    int nb = (b2 >> 4) * 256;       // 256-col n tile
#pragma unroll 4
    for (int r = 0; r < 32; r++)
        ts[r][tid] = (uint32_t)qw[(size_t)(kkb * 32 + r) * N_DIM + nb + tid];
    __syncthreads();
    int n = nb + tid;
#pragma unroll
    for (int c8 = 0; c8 < 8; c8++) {
        uint32_t outw[4];
#pragma unroll
        for (int j = 0; j < 4; j++)
            outw[j] = interleave_nibbles(ts[c8 * 4 + j][tid]);
        *reinterpret_cast<uint4*>(&g_RQ[(size_t)n * QROWS + kkb * 32 + c8 * 4]) =
            *reinterpret_cast<uint4*>(outw);
    }
}

// ---------------------------------------------------------------------------
// Fused int4 GEMM: C = x * dequant(qweight) + bias.
// 128x128x64 tile, 8 warps (2x4), 4-stage cp.async, repacked-B register dequant.
// ---------------------------------------------------------------------------
__device__ __forceinline__ void cp16(uint32_t s, const void* g) {
    asm volatile("cp.async.cg.shared.global [%0], [%1], 16;\n" ::"r"(s), "l"(g) : "memory");
}

__device__ __forceinline__ void issue_tile(int tid, uint32_t sa, uint32_t sb,
                                           const __half* Ag, const uint32_t* rqg,
                                           int kt) {
    int k0 = kt * BK;
#pragma unroll
    for (int t = 0; t < 4; t++) {               // A: 128 rows x 8 chunks
        int ci = tid + t * 256;
        int ar = ci >> 3, ac = (ci & 7) << 3;
        cp16(sa + (ar * A_ST + ac) * 2, Ag + (size_t)ar * K_DIM + k0 + ac);
    }
    {                                           // B: 128 n-rows x 8 words (2 chunks/row)
        int nl = tid >> 1, half = tid & 1;
        cp16(sb + nl * 32 + half * 16, rqg + (size_t)nl * QROWS + kt * 8 + half * 4);
    }
    asm volatile("cp.async.commit_group;\n" ::: "memory");
}

__device__ __forceinline__ void load_afrags(uint32_t sa, int wm, int lane, int ks,
                                            uint32_t af[4][4]) {
#pragma unroll
    for (int mi = 0; mi < 4; mi++) {
        int m = wm * 64 + mi * 16 + (lane & 15);
        int kc = ks * 16 + ((lane >> 4) << 3);
        uint32_t addr = sa + (m * A_ST + kc) * 2;
        asm volatile("ldmatrix.sync.aligned.m8n8.x4.shared.b16 {%0,%1,%2,%3}, [%4];\n"
                     : "=r"(af[mi][0]), "=r"(af[mi][1]), "=r"(af[mi][2]), "=r"(af[mi][3])
                     : "r"(addr));
    }
}

// raw[2ni] = word kk=2ks, raw[2ni+1] = word kk=2ks+1 for column n(ni).
__device__ __forceinline__ void lds_raw(uint32_t sb_nbase, int ks, uint32_t raw[8]) {
#pragma unroll
    for (int ni = 0; ni < 4; ni++) {
        uint32_t addr = sb_nbase + ni * (8 * 32) + ks * 8;
        asm volatile("ld.shared.v2.u32 {%0, %1}, [%2];"
                     : "=r"(raw[2 * ni]), "=r"(raw[2 * ni + 1])
                     : "r"(addr));
    }
}

__device__ __forceinline__ void decode_bf(const uint32_t raw[8], uint32_t sh,
                                          const __half2 hz[4], const __half2 hs[4],
                                          uint32_t bf[8]) {
#pragma unroll
    for (int ni = 0; ni < 4; ni++) {
        uint32_t t0 = raw[2 * ni] >> sh;
        uint32_t t1 = raw[2 * ni + 1] >> sh;
        uint32_t p0 = (t0 & 0x000F000Fu) | 0x64006400u;   // (1024+q_k, 1024+q_{k+1})
        uint32_t p1 = (t1 & 0x000F000Fu) | 0x64006400u;   // (1024+q_{k+8}, ...)
        __half2 v0 = __hmul2(__hsub2(*reinterpret_cast<__half2*>(&p0), hz[ni]), hs[ni]);
        __half2 v1 = __hmul2(__hsub2(*reinterpret_cast<__half2*>(&p1), hz[ni]), hs[ni]);
        bf[2 * ni] = *reinterpret_cast<uint32_t*>(&v0);
        bf[2 * ni + 1] = *reinterpret_cast<uint32_t*>(&v1);
    }
}

__device__ __forceinline__ void do_mmas(const uint32_t af[4][4], const uint32_t bf[8],
                                        float acc[4][4][4]) {
#pragma unroll
    for (int mi = 0; mi < 4; mi++)
#pragma unroll
        for (int ni = 0; ni < 4; ni++) {
            asm volatile(
                "mma.sync.aligned.m16n8k16.row.col.f32.f16.f16.f32 "
                "{%0,%1,%2,%3}, {%4,%5,%6,%7}, {%8,%9}, {%0,%1,%2,%3};\n"
                : "+f"(acc[mi][ni][0]), "+f"(acc[mi][ni][1]), "+f"(acc[mi][ni][2]),
                  "+f"(acc[mi][ni][3])
                : "r"(af[mi][0]), "r"(af[mi][1]), "r"(af[mi][2]), "r"(af[mi][3]),
                  "r"(bf[2 * ni]), "r"(bf[2 * ni + 1]));
        }
}

__global__ void __launch_bounds__(256, 2)
gemm_kernel(const int* __restrict__ qz, const float* __restrict__ sc,
            const float* __restrict__ bias, float* __restrict__ C) {
    extern __shared__ __align__(16) char smem[];

    const int tid = threadIdx.x;
    const int lane = tid & 31;
    const int warp = tid >> 5;
    const int wm = warp >> 2;   // 0..1
    const int wn = warp & 3;    // 0..3
    const int bn = blockIdx.x;
    const int bm = blockIdx.y;
    const uint32_t sh = (lane & 3) * 4;

    const __half* Ag = g_X + (size_t)bm * BM * K_DIM;
    const uint32_t* rqg = g_RQ + (size_t)(bn * BN) * QROWS;

    uint32_t sA[NSTAGE], sBn[NSTAGE];
    const int nb0 = wn * 32 + (lane >> 2);      // base local column for this thread
#pragma unroll
    for (int s = 0; s < NSTAGE; s++) {
        sA[s] = (uint32_t)__cvta_generic_to_shared(smem + s * STAGE_BYTES);
        sBn[s] = sA[s] + A_TILE_H * 2 + nb0 * 32;
    }

    float acc[4][4][4];
#pragma unroll
    for (int i = 0; i < 4; i++)
#pragma unroll
        for (int j = 0; j < 4; j++)
#pragma unroll
            for (int k = 0; k < 4; k++) acc[i][j][k] = 0.0f;

    const int NKI = K_DIM / BK;  // 64
    issue_tile(tid, sA[0], sA[0] + A_TILE_H * 2, Ag, rqg, 0);
    issue_tile(tid, sA[1], sA[1] + A_TILE_H * 2, Ag, rqg, 1);
    issue_tile(tid, sA[2], sA[2] + A_TILE_H * 2, Ag, rqg, 2);

    uint32_t af[4][4], raw[2][8], bf[8];
    __half2 hz[4], hs[4];

    for (int kt = 0; kt < NKI; kt++) {
        if ((kt & 1) == 0) {                    // group = kt/2 zeros+scales
            int g = kt >> 1;
#pragma unroll
            for (int ni = 0; ni < 4; ni++) {
                int n = bn * BN + wn * 32 + ni * 8 + (lane >> 2);
                int z = (qz[g * (N_DIM / 8) + (n >> 3)] >> ((n & 7) * 4)) & 15;
                hz[ni] = __half2half2(__int2half_rn(1024 + z));
                hs[ni] = __half2half2(__float2half_rn(sc[g * N_DIM + n]));
            }
        }

        asm volatile("cp.async.wait_group 2;\n" ::: "memory");
        __syncthreads();
        int cur = kt % NSTAGE;

        lds_raw(sBn[cur], 0, raw[0]);
        if (kt + 3 < NKI)
            issue_tile(tid, sA[(kt + 3) % NSTAGE], sA[(kt + 3) % NSTAGE] + A_TILE_H * 2,
                       Ag, rqg, kt + 3);

#pragma unroll
        for (int ks = 0; ks < 4; ks++) {
            load_afrags(sA[cur], wm, lane, ks, af);
            if (ks < 3) lds_raw(sBn[cur], ks + 1, raw[(ks + 1) & 1]);
            decode_bf(raw[ks & 1], sh, hz, hs, bf);
            do_mmas(af, bf, acc);
        }
    }

    // Epilogue: fp16(acc) + fp16(bias) in fp16 (reference semantics), widen to fp32.
#pragma unroll
    for (int mi = 0; mi < 4; mi++) {
        int r = bm * BM + wm * 64 + mi * 16 + (lane >> 2);
#pragma unroll
        for (int ni = 0; ni < 4; ni++) {
            int col = bn * BN + wn * 32 + ni * 8 + (lane & 3) * 2;
            __half b0 = __float2half_rn(bias[col]);
            __half b1 = __float2half_rn(bias[col + 1]);
            float2 v0, v1;
            v0.x = __half2float(__hadd(__float2half_rn(acc[mi][ni][0]), b0));
            v0.y = __half2float(__hadd(__float2half_rn(acc[mi][ni][1]), b1));
            v1.x = __half2float(__hadd(__float2half_rn(acc[mi][ni][2]), b0));
            v1.y = __half2float(__hadd(__float2half_rn(acc[mi][ni][3]), b1));
            *reinterpret_cast<float2*>(C + (size_t)r * N_DIM + col) = v0;
            *reinterpret_cast<float2*>(C + (size_t)(r + 8) * N_DIM + col) = v1;
        }
    }
}

extern "C" void kernel_launch(void* const* d_in, const int* in_sizes, int n_in,
                              void* d_out, int out_size) {
    const float* x = nullptr;
    const int* qw = nullptr;
    const int* qz = nullptr;
    const float* sc = nullptr;
    const float* bias = nullptr;
    for (int i = 0; i < n_in; i++) {
        int sz = in_sizes[i];
        if (sz == QROWS * N_DIM) qw = (const int*)d_in[i];
        else if (sz == 32 * (N_DIM / 8)) qz = (const int*)d_in[i];
        else if (sz == 32 * N_DIM) sc = (const float*)d_in[i];
        else if (sz == N_DIM) bias = (const float*)d_in[i];
        else if (sz == M_DIM * K_DIM) x = (const float*)d_in[i];
    }
    float* out = (float*)d_out;

    prep_kernel<<<NCVT + NRP, 256>>>(x, qw);

    cudaFuncSetAttribute(gemm_kernel, cudaFuncAttributeMaxDynamicSharedMemorySize,
                         SMEM_BYTES);
    dim3 g_grid(N_DIM / BN, M_DIM / BM);  // (86, 32)
    gemm_kernel<<<g_grid, 256, SMEM_BYTES>>>(qz, sc, bias, out);
}

// round 14
// speedup vs baseline: 1.0321x; 1.0039x over previous
#include <cuda_runtime.h>
#include <cuda_fp16.h>
#include <cstdint>
#include <cstddef>

#define K_DIM 4096
#define N_DIM 11008
#define M_DIM 4096
#define QROWS (K_DIM / 8)

#define BM 128
#define BN 128
#define BK 64
#define A_ST (BK + 8)                 // 72 halves = 144B stride, conflict-free
#define A_TILE_H (BM * A_ST)          // 9216 halves = 18432 B
#define B_TILE_BYTES 4096             // 128 n-rows x 8 repacked words x 4B
#define NSTAGE 4
#define STAGE_BYTES (A_TILE_H * 2 + B_TILE_BYTES)   // 22528
#define SMEM_BYTES (NSTAGE * STAGE_BYTES)           // 90112

// Device-code-only globals (host symbol address = ATS host shadow = zeros!).
__device__ __half g_X[(size_t)M_DIM * K_DIM];        // x as fp16 [M, K]
__device__ uint32_t g_RQ[(size_t)N_DIM * QROWS];     // repacked qweight [N][QROWS]

// ---------------------------------------------------------------------------
// Prep: blocks [0,NCVT) convert x fp32->fp16; blocks [NCVT,+NRP) repack
// qweight into [n][kk] n-major with nibble interleave:
//   rw low16  = q0|q2<<4|q4<<8|q6<<12,  rw high16 = q1|q3<<4|q5<<8|q7<<12
// so (rw>>4c) & 0x000F000F == (q_{2c}, q_{2c+1}) — one SHF+LOP3 per half2.
// ---------------------------------------------------------------------------
#define NCVT (M_DIM * K_DIM / 1024)   // 16384
#define NRP (16 * 43)                 // kk-tiles(512/32) x n-tiles(11008/256)

__device__ __forceinline__ uint32_t interleave_nibbles(uint32_t w) {
    uint32_t e = w & 0x0F0F0F0Fu;
    e = e | (e >> 4); e &= 0x00FF00FFu; e = e | (e >> 8);
    uint32_t o = (w >> 4) & 0x0F0F0F0Fu;
    o = o | (o >> 4); o &= 0x00FF00FFu; o = o | (o >> 8);
    return (e & 0xFFFFu) | (o << 16);
}

__global__ void prep_kernel(const float* __restrict__ x, const int* __restrict__ qw) {
    __shared__ uint32_t ts[32][257];
    int b = blockIdx.x;
    int tid = threadIdx.x;
    if (b < NCVT) {
        size_t i = ((size_t)b * 256 + tid) * 4;
        float4 v = *reinterpret_cast<const float4*>(x + i);
        *reinterpret_cast<__half2*>(&g_X[i]) = __floats2half2_rn(v.x, v.y);
        *reinterpret_cast<__half2*>(&g_X[i + 2]) = __floats2half2_rn(v.z, v.w);
        return;
    }
    int b2 = b - NCVT;
    int kkb = b2 & 15;              // 32-row kk tile
    int nb = (b2 >> 4) * 256;       // 256-col n tile
#pragma unroll 4
    for (int r = 0; r < 32; r++)
        ts[r][tid] = (uint32_t)qw[(size_t)(kkb * 32 + r) * N_DIM + nb + tid];
    __syncthreads();
    int n = nb + tid;
#pragma unroll
    for (int c8 = 0; c8 < 8; c8++) {
        uint32_t outw[4];
#pragma unroll
        for (int j = 0; j < 4; j++)
            outw[j] = interleave_nibbles(ts[c8 * 4 + j][tid]);
        *reinterpret_cast<uint4*>(&g_RQ[(size_t)n * QROWS + kkb * 32 + c8 * 4]) =
            *reinterpret_cast<uint4*>(outw);
    }
}

// ---------------------------------------------------------------------------
// Fused int4 GEMM: C = x * dequant(qweight) + bias.
// 128x128x64 tile, 8 warps (2x4), 4-stage cp.async, double-buffered af/raw,
// just-in-time per-ni B decode fused into the MMA loop.
// ---------------------------------------------------------------------------
__device__ __forceinline__ void cp16(uint32_t s, const void* g) {
    asm volatile("cp.async.cg.shared.global [%0], [%1], 16;\n" ::"r"(s), "l"(g) : "memory");
}

__device__ __forceinline__ void issue_tile(int tid, uint32_t sa, uint32_t sb,
                                           const __half* Ag, const uint32_t* rqg,
                                           int kt) {
    int k0 = kt * BK;
#pragma unroll
    for (int t = 0; t < 4; t++) {               // A: 128 rows x 8 chunks
        int ci = tid + t * 256;
        int ar = ci >> 3, ac = (ci & 7) << 3;
        cp16(sa + (ar * A_ST + ac) * 2, Ag + (size_t)ar * K_DIM + k0 + ac);
    }
    {                                           // B: 128 n-rows x 8 words (2 chunks/row)
        int nl = tid >> 1, half = tid & 1;
        cp16(sb + nl * 32 + half * 16, rqg + (size_t)nl * QROWS + kt * 8 + half * 4);
    }
    asm volatile("cp.async.commit_group;\n" ::: "memory");
}

__device__ __forceinline__ void load_afrags(uint32_t sa, int wm, int lane, int ks,
                                            uint32_t af[4][4]) {
#pragma unroll
    for (int mi = 0; mi < 4; mi++) {
        int m = wm * 64 + mi * 16 + (lane & 15);
        int kc = ks * 16 + ((lane >> 4) << 3);
        uint32_t addr = sa + (m * A_ST + kc) * 2;
        asm volatile("ldmatrix.sync.aligned.m8n8.x4.shared.b16 {%0,%1,%2,%3}, [%4];\n"
                     : "=r"(af[mi][0]), "=r"(af[mi][1]), "=r"(af[mi][2]), "=r"(af[mi][3])
                     : "r"(addr));
    }
}

// raw[2ni] = word kk=2ks, raw[2ni+1] = word kk=2ks+1 for column n(ni).
__device__ __forceinline__ void lds_raw(uint32_t sb_nbase, int ks, uint32_t raw[8]) {
#pragma unroll
    for (int ni = 0; ni < 4; ni++) {
        uint32_t addr = sb_nbase + ni * (8 * 32) + ks * 8;
        asm volatile("ld.shared.v2.u32 {%0, %1}, [%2];"
                     : "=r"(raw[2 * ni]), "=r"(raw[2 * ni + 1])
                     : "r"(addr));
    }
}

// Per-ni: decode two B-fragment regs (exact: (1024+q)-(1024+z), then one
// fp16 multiply by s), immediately consumed by 4 MMAs.
__device__ __forceinline__ void decode_mma(const uint32_t raw[8],
                                           const uint32_t af[4][4], uint32_t sh,
                                           const __half2 hz[4], const __half2 hs[4],
                                           float acc[4][4][4]) {
#pragma unroll
    for (int ni = 0; ni < 4; ni++) {
        uint32_t t0 = raw[2 * ni] >> sh;
        uint32_t t1 = raw[2 * ni + 1] >> sh;
        uint32_t p0 = (t0 & 0x000F000Fu) | 0x64006400u;
        uint32_t p1 = (t1 & 0x000F000Fu) | 0x64006400u;
        __half2 v0 = __hmul2(__hsub2(*reinterpret_cast<__half2*>(&p0), hz[ni]), hs[ni]);
        __half2 v1 = __hmul2(__hsub2(*reinterpret_cast<__half2*>(&p1), hz[ni]), hs[ni]);
        uint32_t b0 = *reinterpret_cast<uint32_t*>(&v0);
        uint32_t b1 = *reinterpret_cast<uint32_t*>(&v1);
#pragma unroll
        for (int mi = 0; mi < 4; mi++) {
            asm volatile(
                "mma.sync.aligned.m16n8k16.row.col.f32.f16.f16.f32 "
                "{%0,%1,%2,%3}, {%4,%5,%6,%7}, {%8,%9}, {%0,%1,%2,%3};\n"
                : "+f"(acc[mi][ni][0]), "+f"(acc[mi][ni][1]), "+f"(acc[mi][ni][2]),
                  "+f"(acc[mi][ni][3])
                : "r"(af[mi][0]), "r"(af[mi][1]), "r"(af[mi][2]), "r"(af[mi][3]),
                  "r"(b0), "r"(b1));
        }
    }
}

__global__ void __launch_bounds__(256, 2)
gemm_kernel(const int* __restrict__ qz, const float* __restrict__ sc,
            const float* __restrict__ bias, float* __restrict__ C) {
    extern __shared__ __align__(16) char smem[];

    const int tid = threadIdx.x;
    const int lane = tid & 31;
    const int warp = tid >> 5;
    const int wm = warp >> 2;   // 0..1
    const int wn = warp & 3;    // 0..3
    const int bn = blockIdx.x;
    const int bm = blockIdx.y;
    const uint32_t sh = (lane & 3) * 4;

    const __half* Ag = g_X + (size_t)bm * BM * K_DIM;
    const uint32_t* rqg = g_RQ + (size_t)(bn * BN) * QROWS;

    uint32_t sA[NSTAGE], sBn[NSTAGE];
    const int nb0 = wn * 32 + (lane >> 2);      // base local column for this thread
#pragma unroll
    for (int s = 0; s < NSTAGE; s++) {
        sA[s] = (uint32_t)__cvta_generic_to_shared(smem + s * STAGE_BYTES);
        sBn[s] = sA[s] + A_TILE_H * 2 + nb0 * 32;
    }

    float acc[4][4][4];
#pragma unroll
    for (int i = 0; i < 4; i++)
#pragma unroll
        for (int j = 0; j < 4; j++)
#pragma unroll
            for (int k = 0; k < 4; k++) acc[i][j][k] = 0.0f;

    const int NKI = K_DIM / BK;  // 64
    issue_tile(tid, sA[0], sA[0] + A_TILE_H * 2, Ag, rqg, 0);
    issue_tile(tid, sA[1], sA[1] + A_TILE_H * 2, Ag, rqg, 1);
    issue_tile(tid, sA[2], sA[2] + A_TILE_H * 2, Ag, rqg, 2);

    uint32_t af[2][4][4], raw[2][8];
    __half2 hz[4], hs[4];

    for (int kt = 0; kt < NKI; kt++) {
        if ((kt & 1) == 0) {                    // group = kt/2 zeros+scales
            int g = kt >> 1;
#pragma unroll
            for (int ni = 0; ni < 4; ni++) {
                int n = bn * BN + wn * 32 + ni * 8 + (lane >> 2);
                int z = (qz[g * (N_DIM / 8) + (n >> 3)] >> ((n & 7) * 4)) & 15;
                hz[ni] = __half2half2(__int2half_rn(1024 + z));
                hs[ni] = __half2half2(__float2half_rn(sc[g * N_DIM + n]));
            }
        }

        asm volatile("cp.async.wait_group 2;\n" ::: "memory");
        __syncthreads();
        int cur = kt % NSTAGE;

        // Stage-entry prefetch for ks=0.
        lds_raw(sBn[cur], 0, raw[0]);
        load_afrags(sA[cur], wm, lane, 0, af[0]);

        if (kt + 3 < NKI)
            issue_tile(tid, sA[(kt + 3) % NSTAGE], sA[(kt + 3) % NSTAGE] + A_TILE_H * 2,
                       Ag, rqg, kt + 3);

#pragma unroll
        for (int ks = 0; ks < 4; ks++) {
            if (ks < 3) {
                lds_raw(sBn[cur], ks + 1, raw[(ks + 1) & 1]);
                load_afrags(sA[cur], wm, lane, ks + 1, af[(ks + 1) & 1]);
            }
            decode_mma(raw[ks & 1], af[ks & 1], sh, hz, hs, acc);
        }
    }

    // Epilogue: fp16(acc) + fp16(bias) in fp16 (reference semantics), widen to fp32.
#pragma unroll
    for (int mi = 0; mi < 4; mi++) {
        int r = bm * BM + wm * 64 + mi * 16 + (lane >> 2);
#pragma unroll
        for (int ni = 0; ni < 4; ni++) {
            int col = bn * BN + wn * 32 + ni * 8 + (lane & 3) * 2;
            __half b0 = __float2half_rn(bias[col]);
            __half b1 = __float2half_rn(bias[col + 1]);
            float2 v0, v1;
            v0.x = __half2float(__hadd(__float2half_rn(acc[mi][ni][0]), b0));
            v0.y = __half2float(__hadd(__float2half_rn(acc[mi][ni][1]), b1));
            v1.x = __half2float(__hadd(__float2half_rn(acc[mi][ni][2]), b0));
            v1.y = __half2float(__hadd(__float2half_rn(acc[mi][ni][3]), b1));
            *reinterpret_cast<float2*>(C + (size_t)r * N_DIM + col) = v0;
            *reinterpret_cast<float2*>(C + (size_t)(r + 8) * N_DIM + col) = v1;
        }
    }
}

extern "C" void kernel_launch(void* const* d_in, const int* in_sizes, int n_in,
                              void* d_out, int out_size) {
    const float* x = nullptr;
    const int* qw = nullptr;
    const int* qz = nullptr;
    const float* sc = nullptr;
    const float* bias = nullptr;
    for (int i = 0; i < n_in; i++) {
        int sz = in_sizes[i];
        if (sz == QROWS * N_DIM) qw = (const int*)d_in[i];
        else if (sz == 32 * (N_DIM / 8)) qz = (const int*)d_in[i];
        else if (sz == 32 * N_DIM) sc = (const float*)d_in[i];
        else if (sz == N_DIM) bias = (const float*)d_in[i];
        else if (sz == M_DIM * K_DIM) x = (const float*)d_in[i];
    }
    float* out = (float*)d_out;

    prep_kernel<<<NCVT + NRP, 256>>>(x, qw);

    cudaFuncSetAttribute(gemm_kernel, cudaFuncAttributeMaxDynamicSharedMemorySize,
                         SMEM_BYTES);
    dim3 g_grid(N_DIM / BN, M_DIM / BM);  // (86, 32)
    gemm_kernel<<<g_grid, 256, SMEM_BYTES>>>(qz, sc, bias, out);
}

// round 15
// speedup vs baseline: 1.2309x; 1.1927x over previous
#include <cuda_runtime.h>
#include <cuda_fp16.h>
#include <cstdint>
#include <cstddef>

#define K_DIM 4096
#define N_DIM 11008
#define M_DIM 4096
#define QROWS (K_DIM / 8)

#define BM 128
#define BN 128
#define BK 64
#define A_ST (BK + 8)            // 72 halves = 144B stride (conflict-free ldmatrix)
#define B_ST (BN + 8)            // 136 halves = 272B stride
#define NSTAGE 3
#define A_TILE_H (BM * A_ST)     // 9216 halves
#define B_TILE_H (BK * B_ST)     // 8704 halves
#define STAGE_H (A_TILE_H + B_TILE_H)      // 17920 halves = 35840 B
#define SMEM_BYTES (NSTAGE * STAGE_H * 2)  // 107520 B

// Device-code-only globals (host symbol address = ATS host shadow = zeros!).
__device__ __half g_W[(size_t)K_DIM * N_DIM];    // dequantized W [K, N]
__device__ __half g_X[(size_t)M_DIM * K_DIM];    // x as fp16 [M, K]

// ---------------------------------------------------------------------------
// Prep (fused, one launch): blocks [0,NCVT) convert x fp32->fp16,
// blocks [NCVT, NCVT+NDQ) dequantize int4 weights into g_W.
// ---------------------------------------------------------------------------
#define NCVT (M_DIM * K_DIM / 1024)              // 16384
#define DQ_CBLK (N_DIM / 256)                    // 43
#define NDQ (DQ_CBLK * QROWS)                    // 22016

__global__ void prep_kernel(const float* __restrict__ x,
                            const int* __restrict__ qw,
                            const int* __restrict__ qz,
                            const float* __restrict__ sc) {
    int b = blockIdx.x;
    if (b < NCVT) {
        size_t i = ((size_t)b * 256 + threadIdx.x) * 4;
        float4 v = *reinterpret_cast<const float4*>(x + i);
        *reinterpret_cast<__half2*>(&g_X[i]) = __floats2half2_rn(v.x, v.y);
        *reinterpret_cast<__half2*>(&g_X[i + 2]) = __floats2half2_rn(v.z, v.w);
        return;
    }
    b -= NCVT;
    int c = (b % DQ_CBLK) * 256 + threadIdx.x;
    int kk = b / DQ_CBLK;
    if (c >= N_DIM) return;
    int packed = qw[kk * N_DIM + c];
    int g = kk >> 4;
    int z = (qz[g * (N_DIM / 8) + (c >> 3)] >> ((c & 7) * 4)) & 15;
    float s = sc[g * N_DIM + c];
    size_t base = (size_t)kk * 8 * N_DIM + c;
#pragma unroll
    for (int i = 0; i < 8; i++) {
        int q = (packed >> (i * 4)) & 15;
        g_W[base + (size_t)i * N_DIM] = __float2half((float)(q - z) * s);
    }
}

// ---------------------------------------------------------------------------
// GEMM: 128x128x64 tile, 8 warps (2x4), 3-stage cp.async (wait_group 1),
// 4 ks-steps per iteration, register double-buffered fragments.
// Grid is bm-major: a wave covers all 32 bm x ~9 bn, so the B panel is
// fetched into L2 once per wave and reused 32x.
// ---------------------------------------------------------------------------
__device__ __forceinline__ void cp16(uint32_t s, const void* g) {
    asm volatile("cp.async.cg.shared.global [%0], [%1], 16;\n" ::"r"(s), "l"(g) : "memory");
}

__device__ __forceinline__ void issue_tile(int tid, uint32_t sa, uint32_t sb,
                                           const __half* Ag, const __half* Bg,
                                           int k0) {
#pragma unroll
    for (int t = 0; t < 4; t++) {               // A: 128 rows x 8 chunks = 1024
        int ci = tid + t * 256;
        int ar = ci >> 3, ac = (ci & 7) << 3;
        cp16(sa + (ar * A_ST + ac) * 2, Ag + (size_t)ar * K_DIM + k0 + ac);
    }
#pragma unroll
    for (int t = 0; t < 4; t++) {               // B: 64 rows x 16 chunks = 1024
        int ci = tid + t * 256;
        int br = ci >> 4, bc = (ci & 15) << 3;
        cp16(sb + (br * B_ST + bc) * 2, Bg + (size_t)(k0 + br) * N_DIM + bc);
    }
    asm volatile("cp.async.commit_group;\n" ::: "memory");
}

__device__ __forceinline__ void load_frags(uint32_t sa, uint32_t sb, int wm, int wn,
                                           int lane, int ks, uint32_t af[4][4],
                                           uint32_t bf[2][4]) {
#pragma unroll
    for (int mi = 0; mi < 4; mi++) {
        int m = wm * 64 + mi * 16 + (lane & 15);
        int kc = ks * 16 + ((lane >> 4) << 3);
        uint32_t addr = sa + (m * A_ST + kc) * 2;
        asm volatile("ldmatrix.sync.aligned.m8n8.x4.shared.b16 {%0,%1,%2,%3}, [%4];\n"
                     : "=r"(af[mi][0]), "=r"(af[mi][1]), "=r"(af[mi][2]), "=r"(af[mi][3])
                     : "r"(addr));
    }
#pragma unroll
    for (int nj = 0; nj < 2; nj++) {
        int kr = ks * 16 + (lane & 15);
        int n = wn * 32 + nj * 16 + ((lane >> 4) << 3);
        uint32_t addr = sb + (kr * B_ST + n) * 2;
        asm volatile("ldmatrix.sync.aligned.m8n8.x4.trans.shared.b16 {%0,%1,%2,%3}, [%4];\n"
                     : "=r"(bf[nj][0]), "=r"(bf[nj][1]), "=r"(bf[nj][2]), "=r"(bf[nj][3])
                     : "r"(addr));
    }
}

__device__ __forceinline__ void do_mmas(const uint32_t af[4][4], const uint32_t bf[2][4],
                                        float acc[4][4][4]) {
#pragma unroll
    for (int mi = 0; mi < 4; mi++)
#pragma unroll
        for (int ni = 0; ni < 4; ni++) {
            uint32_t b0 = bf[ni >> 1][(ni & 1) * 2];
            uint32_t b1 = bf[ni >> 1][(ni & 1) * 2 + 1];
            asm volatile(
                "mma.sync.aligned.m16n8k16.row.col.f32.f16.f16.f32 "
                "{%0,%1,%2,%3}, {%4,%5,%6,%7}, {%8,%9}, {%0,%1,%2,%3};\n"
                : "+f"(acc[mi][ni][0]), "+f"(acc[mi][ni][1]), "+f"(acc[mi][ni][2]),
                  "+f"(acc[mi][ni][3])
                : "r"(af[mi][0]), "r"(af[mi][1]), "r"(af[mi][2]), "r"(af[mi][3]),
                  "r"(b0), "r"(b1));
        }
}

__global__ void __launch_bounds__(256, 2)
gemm_kernel(const float* __restrict__ bias, float* __restrict__ C) {
    extern __shared__ __align__(16) __half smem[];

    const int tid = threadIdx.x;
    const int lane = tid & 31;
    const int warp = tid >> 5;
    const int wm = warp >> 2;   // 0..1
    const int wn = warp & 3;    // 0..3
    const int bm = blockIdx.x;  // bm-major: wave = all bm x few bn
    const int bn = blockIdx.y;

    const __half* Ag = g_X + (size_t)bm * BM * K_DIM;
    const __half* Bg = g_W + (size_t)bn * BN;

    uint32_t sA[NSTAGE], sB[NSTAGE];
#pragma unroll
    for (int s = 0; s < NSTAGE; s++) {
        sA[s] = (uint32_t)__cvta_generic_to_shared(smem + s * STAGE_H);
        sB[s] = sA[s] + A_TILE_H * 2;
    }

    float acc[4][4][4];
#pragma unroll
    for (int i = 0; i < 4; i++)
#pragma unroll
        for (int j = 0; j < 4; j++)
#pragma unroll
            for (int k = 0; k < 4; k++) acc[i][j][k] = 0.0f;

    const int NKI = K_DIM / BK;  // 64
    issue_tile(tid, sA[0], sB[0], Ag, Bg, 0);
    issue_tile(tid, sA[1], sB[1], Ag, Bg, BK);

    uint32_t af[2][4][4], bf[2][2][4];

    for (int kt = 0; kt < NKI; kt++) {
        asm volatile("cp.async.wait_group 1;\n" ::: "memory");
        __syncthreads();
        int cur = kt % NSTAGE;

        load_frags(sA[cur], sB[cur], wm, wn, lane, 0, af[0], bf[0]);

        if (kt + 2 < NKI)
            issue_tile(tid, sA[(kt + 2) % NSTAGE], sB[(kt + 2) % NSTAGE], Ag, Bg,
                       (kt + 2) * BK);

#pragma unroll
        for (int ks = 0; ks < 4; ks++) {
            if (ks < 3)
                load_frags(sA[cur], sB[cur], wm, wn, lane, ks + 1, af[(ks + 1) & 1],
                           bf[(ks + 1) & 1]);
            do_mmas(af[ks & 1], bf[ks & 1], acc);
        }
    }

    // Epilogue: fp16(acc) + fp16(bias) in fp16 (reference semantics), widen to fp32.
#pragma unroll
    for (int mi = 0; mi < 4; mi++) {
        int r = bm * BM + wm * 64 + mi * 16 + (lane >> 2);
#pragma unroll
        for (int ni = 0; ni < 4; ni++) {
            int col = bn * BN + wn * 32 + ni * 8 + (lane & 3) * 2;
            __half b0 = __float2half_rn(bias[col]);
            __half b1 = __float2half_rn(bias[col + 1]);
            float2 v0, v1;
            v0.x = __half2float(__hadd(__float2half_rn(acc[mi][ni][0]), b0));
            v0.y = __half2float(__hadd(__float2half_rn(acc[mi][ni][1]), b1));
            v1.x = __half2float(__hadd(__float2half_rn(acc[mi][ni][2]), b0));
            v1.y = __half2float(__hadd(__float2half_rn(acc[mi][ni][3]), b1));
            *reinterpret_cast<float2*>(C + (size_t)r * N_DIM + col) = v0;
            *reinterpret_cast<float2*>(C + (size_t)(r + 8) * N_DIM + col) = v1;
        }
    }
}

extern "C" void kernel_launch(void* const* d_in, const int* in_sizes, int n_in,
                              void* d_out, int out_size) {
    const float* x = nullptr;
    const int* qw = nullptr;
    const int* qz = nullptr;
    const float* sc = nullptr;
    const float* bias = nullptr;
    for (int i = 0; i < n_in; i++) {
        int sz = in_sizes[i];
        if (sz == QROWS * N_DIM) qw = (const int*)d_in[i];
        else if (sz == 32 * (N_DIM / 8)) qz = (const int*)d_in[i];
        else if (sz == 32 * N_DIM) sc = (const float*)d_in[i];
        else if (sz == N_DIM) bias = (const float*)d_in[i];
        else if (sz == M_DIM * K_DIM) x = (const float*)d_in[i];
    }
    float* out = (float*)d_out;

    prep_kernel<<<NCVT + NDQ, 256>>>(x, qw, qz, sc);

    cudaFuncSetAttribute(gemm_kernel, cudaFuncAttributeMaxDynamicSharedMemorySize,
                         SMEM_BYTES);
    dim3 g_grid(M_DIM / BM, N_DIM / BN);  // (32, 86) — bm-major
    gemm_kernel<<<g_grid, 256, SMEM_BYTES>>>(bias, out);
}